// round 10
// baseline (speedup 1.0000x reference)
#include <cuda_runtime.h>
#include <cstdint>

#define DIM 128
#define MAXN 50176
#define BM 128
#define BK 32
#define AP 36                   // padded smem row pitch (words), conflict-free
#define TILEW (BM * AP)         // 4608 words per tile buffer
#define SMEM_BYTES (4 * TILEW * 4)   // 2 A bufs + 2 W bufs = 73728 B
#define NTHREADS 512

__device__ float g_hpre[MAXN * DIM];       // x + agg
__device__ float g_h1[MAXN * DIM];         // Linear1 out (raw, pre-BN)
__device__ float g_stats[2 * DIM];         // colsum | colsumsq
__device__ unsigned g_w1[DIM * DIM];       // tf32-rounded weights
__device__ unsigned g_w2[DIM * DIM];
__device__ unsigned g_wres[DIM * DIM];

// ---------------------------------------------------------------------------
__device__ __forceinline__ unsigned f2tf(float f) {
    unsigned r;
    asm("cvt.rna.tf32.f32 %0, %1;" : "=r"(r) : "f"(f));
    return r;
}

__device__ __forceinline__ void mma_tf32(float* c, const unsigned* a, const unsigned* b) {
    asm volatile(
        "mma.sync.aligned.m16n8k8.row.col.f32.tf32.tf32.f32 "
        "{%0,%1,%2,%3}, {%4,%5,%6,%7}, {%8,%9}, {%0,%1,%2,%3};"
        : "+f"(c[0]), "+f"(c[1]), "+f"(c[2]), "+f"(c[3])
        : "r"(a[0]), "r"(a[1]), "r"(a[2]), "r"(a[3]), "r"(b[0]), "r"(b[1]));
}

__device__ __forceinline__ void cp16(unsigned smem_dst, const void* gsrc) {
    asm volatile("cp.async.ca.shared.global [%0], [%1], 16;"
                 :: "r"(smem_dst), "l"(gsrc));
}

__device__ __forceinline__ void ldsm4(unsigned& r0, unsigned& r1,
                                      unsigned& r2, unsigned& r3,
                                      const unsigned* p) {
    unsigned addr = (unsigned)__cvta_generic_to_shared(p);
    asm volatile("ldmatrix.sync.aligned.m8n8.x4.shared.b16 {%0,%1,%2,%3}, [%4];"
                 : "=r"(r0), "=r"(r1), "=r"(r2), "=r"(r3) : "r"(addr));
}

// ---------------------------------------------------------------------------
// init: copy x -> g_hpre ; round weights ; zero stats   (one launch)
// ---------------------------------------------------------------------------
__global__ void init_kernel(const float* __restrict__ x,
                            const float* __restrict__ W1,
                            const float* __restrict__ W2,
                            const float* __restrict__ Wres, int n4) {
    int gid = blockIdx.x * blockDim.x + threadIdx.x;
    if (gid < 2 * DIM) g_stats[gid] = 0.0f;
    if (gid < DIM * DIM) {
        g_w1[gid]   = f2tf(W1[gid]);
        g_w2[gid]   = f2tf(W2[gid]);
        g_wres[gid] = f2tf(Wres[gid]);
    }
    if (gid < n4) ((float4*)g_hpre)[gid] = ((const float4*)x)[gid];
}

// ---------------------------------------------------------------------------
// scatter-add: warp per edge, lane = 4 floats -> LDG.128 + red.global.v4.f32
// ---------------------------------------------------------------------------
__global__ void scatter_kernel(const float* __restrict__ x,
                               const int* __restrict__ ei,
                               int n_edges) {
    int g = blockIdx.x * blockDim.x + threadIdx.x;
    int e = g >> 5;
    int lane = g & 31;
    if (e >= n_edges) return;
    int src = ei[e];
    int dst = ei[n_edges + e];
    const float4* xs = (const float4*)(x + (size_t)src * DIM) + lane;
    float4* hd = (float4*)(g_hpre + (size_t)dst * DIM) + lane;
    float4 v = __ldg(xs);
    asm volatile("red.global.add.v4.f32 [%0], {%1, %2, %3, %4};"
                 :: "l"(hd), "f"(v.x), "f"(v.y), "f"(v.z), "f"(v.w)
                 : "memory");
}

// ---------------------------------------------------------------------------
// Pipelined tf32 GEMM: 512 threads, 16 warps 4x4, 32x32 warp tiles.
// PHASE 1: h1 = h_pre @ W1^T + b1 ; BN column sum/sumsq        (K=128)
// PHASE 2: out = lrelu_.2( bnlrelu(h1) @ W2^T + x @ Wres^T + b2 )  (K=256)
// ---------------------------------------------------------------------------
template <int PHASE>
__global__ __launch_bounds__(NTHREADS, 2)
void gemm_kernel(const float* __restrict__ Ax,      // phase2: x
                 const float* __restrict__ bias,
                 const float* __restrict__ gamma,
                 const float* __restrict__ beta,
                 float* __restrict__ outp,
                 int M, float invM) {
    extern __shared__ unsigned smem[];
    unsigned* Abuf = smem;                 // [2][TILEW]
    unsigned* Wbuf = smem + 2 * TILEW;     // [2][TILEW]
    __shared__ float s_sum[DIM];
    __shared__ float s_sq[DIM];
    __shared__ float ssc[DIM];
    __shared__ float ssh[DIM];

    const int tid  = threadIdx.x;
    const int wid  = tid >> 5;
    const int lane = tid & 31;
    const int g    = lane >> 2;
    const int tg   = lane & 3;
    const int lm   = lane >> 3;        // ldmatrix: matrix id 0..3
    const int lr   = lane & 7;         // ldmatrix: row within matrix
    const int wm   = wid & 3;          // m tile of 32
    const int wn   = wid >> 2;         // n tile of 32
    const int rowBase = blockIdx.x * BM;

    if (PHASE == 1) {
        if (tid < DIM) { s_sum[tid] = 0.f; s_sq[tid] = 0.f; }
    } else {
        if (tid < DIM) {
            float mu  = g_stats[tid] * invM;
            float var = g_stats[DIM + tid] * invM - mu * mu;
            float rstd = rsqrtf(var + 1e-5f);
            float s = gamma[tid] * rstd;
            ssc[tid] = s;
            ssh[tid] = beta[tid] - mu * s;
        }
    }

    const int NCHUNK = (PHASE == 1) ? 4 : 8;

    // ---- chunk loader: 2 x 16B cp.async for A, 2 for W per thread ----
    auto load_chunk = [&](int kc, int bufidx) {
        const int kbase = kc * BK;
        unsigned* Ad = Abuf + bufidx * TILEW;
        unsigned* Wd = Wbuf + bufidx * TILEW;
#pragma unroll
        for (int t = 0; t < 2; t++) {
            int idx = tid + t * NTHREADS;
            int m = idx >> 3;
            int f4 = (idx & 7) * 4;
            const void* asrc;
            if (PHASE == 1) {
                asrc = g_hpre + (size_t)(rowBase + m) * DIM + kbase + f4;
            } else if (kbase < DIM) {
                asrc = g_h1 + (size_t)(rowBase + m) * DIM + kbase + f4;
            } else {
                int gr = rowBase + m;
                if (gr >= M) gr = M - 1;           // x has exactly M rows
                asrc = Ax + (size_t)gr * DIM + (kbase - DIM) + f4;
            }
            cp16((unsigned)__cvta_generic_to_shared(Ad + m * AP + f4), asrc);
            const unsigned* wsrc;
            if (PHASE == 1)            wsrc = g_w1   + m * DIM + kbase + f4;
            else if (kbase < DIM)      wsrc = g_w2   + m * DIM + kbase + f4;
            else                       wsrc = g_wres + m * DIM + (kbase - DIM) + f4;
            cp16((unsigned)__cvta_generic_to_shared(Wd + m * AP + f4), wsrc);
        }
        asm volatile("cp.async.commit_group;" ::: "memory");
    };

    float acc[2][4][4];
#pragma unroll
    for (int i = 0; i < 2; i++)
#pragma unroll
        for (int j = 0; j < 4; j++)
#pragma unroll
            for (int r = 0; r < 4; r++) acc[i][j][r] = 0.f;

    load_chunk(0, 0);

#pragma unroll 1
    for (int kc = 0; kc < NCHUNK; kc++) {
        if (kc + 1 < NCHUNK) {
            load_chunk(kc + 1, (kc + 1) & 1);
            asm volatile("cp.async.wait_group 1;" ::: "memory");
        } else {
            asm volatile("cp.async.wait_group 0;" ::: "memory");
        }
        __syncthreads();

        unsigned* As = Abuf + (kc & 1) * TILEW;
        const unsigned* Ws = Wbuf + (kc & 1) * TILEW;

        // ---- phase2, h1 chunks: BN + leaky + tf32-round in smem ----
        if (PHASE == 2 && kc * BK < DIM) {
            const int kbase = kc * BK;
#pragma unroll
            for (int t = 0; t < 2; t++) {
                int idx = tid + t * NTHREADS;
                int m = idx >> 3;
                int f4 = (idx & 7) * 4;
                unsigned* p = As + m * AP + f4;
                float4 v = *(float4*)p;
                int kk = kbase + f4;
                v.x = fmaf(v.x, ssc[kk + 0], ssh[kk + 0]);
                v.y = fmaf(v.y, ssc[kk + 1], ssh[kk + 1]);
                v.z = fmaf(v.z, ssc[kk + 2], ssh[kk + 2]);
                v.w = fmaf(v.w, ssc[kk + 3], ssh[kk + 3]);
                v.x = v.x > 0.f ? v.x : 0.01f * v.x;
                v.y = v.y > 0.f ? v.y : 0.01f * v.y;
                v.z = v.z > 0.f ? v.z : 0.01f * v.z;
                v.w = v.w > 0.f ? v.w : 0.01f * v.w;
                p[0] = f2tf(v.x); p[1] = f2tf(v.y);
                p[2] = f2tf(v.z); p[3] = f2tf(v.w);
            }
            __syncthreads();
        }

#pragma unroll
        for (int k8 = 0; k8 < 4; k8++) {
            const int kof = k8 * 8;
            unsigned afrag[2][4];
#pragma unroll
            for (int mt = 0; mt < 2; mt++) {
                int r = wm * 32 + mt * 16 + (lm & 1) * 8 + lr;
                ldsm4(afrag[mt][0], afrag[mt][1], afrag[mt][2], afrag[mt][3],
                      As + r * AP + kof + (lm >> 1) * 4);
            }
            unsigned bfrag[4][2];
#pragma unroll
            for (int ntp = 0; ntp < 2; ntp++) {
                int n = wn * 32 + ntp * 16 + (lm >> 1) * 8 + lr;
                ldsm4(bfrag[2 * ntp][0], bfrag[2 * ntp][1],
                      bfrag[2 * ntp + 1][0], bfrag[2 * ntp + 1][1],
                      Ws + n * AP + kof + (lm & 1) * 4);
            }
#pragma unroll
            for (int mt = 0; mt < 2; mt++)
#pragma unroll
                for (int nt = 0; nt < 4; nt++)
                    mma_tf32(acc[mt][nt], afrag[mt], bfrag[nt]);
        }
        __syncthreads();
    }

    // ---- epilogue ----
    if (PHASE == 1) {
        float tsum[4][2], tsq[4][2];
#pragma unroll
        for (int nt = 0; nt < 4; nt++)
            tsum[nt][0] = tsum[nt][1] = tsq[nt][0] = tsq[nt][1] = 0.f;

#pragma unroll
        for (int mt = 0; mt < 2; mt++) {
#pragma unroll
            for (int half = 0; half < 2; half++) {
                int gr = rowBase + wm * 32 + mt * 16 + g + half * 8;
                if (gr < M) {
#pragma unroll
                    for (int nt = 0; nt < 4; nt++) {
                        int c = wn * 32 + nt * 8 + tg * 2;
                        float v0 = acc[mt][nt][half * 2 + 0] + __ldg(bias + c);
                        float v1 = acc[mt][nt][half * 2 + 1] + __ldg(bias + c + 1);
                        tsum[nt][0] += v0;  tsum[nt][1] += v1;
                        tsq[nt][0] += v0 * v0;  tsq[nt][1] += v1 * v1;
                        *(float2*)(g_h1 + (size_t)gr * DIM + c) = make_float2(v0, v1);
                    }
                }
            }
        }
#pragma unroll
        for (int nt = 0; nt < 4; nt++) {
#pragma unroll
            for (int h = 0; h < 2; h++) {
#pragma unroll
                for (int ofs = 4; ofs < 32; ofs <<= 1) {
                    tsum[nt][h] += __shfl_xor_sync(0xffffffff, tsum[nt][h], ofs);
                    tsq[nt][h]  += __shfl_xor_sync(0xffffffff, tsq[nt][h], ofs);
                }
            }
        }
        if (g == 0) {
#pragma unroll
            for (int nt = 0; nt < 4; nt++) {
                int c = wn * 32 + nt * 8 + tg * 2;
                atomicAdd(&s_sum[c],     tsum[nt][0]);
                atomicAdd(&s_sum[c + 1], tsum[nt][1]);
                atomicAdd(&s_sq[c],      tsq[nt][0]);
                atomicAdd(&s_sq[c + 1],  tsq[nt][1]);
            }
        }
        __syncthreads();
        if (tid < DIM) {
            atomicAdd(&g_stats[tid],       s_sum[tid]);
            atomicAdd(&g_stats[DIM + tid], s_sq[tid]);
        }
    } else {
#pragma unroll
        for (int mt = 0; mt < 2; mt++) {
#pragma unroll
            for (int half = 0; half < 2; half++) {
                int gr = rowBase + wm * 32 + mt * 16 + g + half * 8;
                if (gr < M) {
#pragma unroll
                    for (int nt = 0; nt < 4; nt++) {
                        int c = wn * 32 + nt * 8 + tg * 2;
                        float v0 = acc[mt][nt][half * 2 + 0] + __ldg(bias + c);
                        float v1 = acc[mt][nt][half * 2 + 1] + __ldg(bias + c + 1);
                        v0 = v0 > 0.f ? v0 : 0.2f * v0;
                        v1 = v1 > 0.f ? v1 : 0.2f * v1;
                        *(float2*)(outp + (size_t)gr * DIM + c) = make_float2(v0, v1);
                    }
                }
            }
        }
    }
}

// ---------------------------------------------------------------------------
extern "C" void kernel_launch(void* const* d_in, const int* in_sizes, int n_in,
                              void* d_out, int out_size) {
    const float* x     = (const float*)d_in[0];
    const int* ei      = (const int*)d_in[1];
    const float* W1    = (const float*)d_in[2];
    const float* b1    = (const float*)d_in[3];
    const float* gamma = (const float*)d_in[4];
    const float* beta  = (const float*)d_in[5];
    const float* W2    = (const float*)d_in[6];
    const float* b2    = (const float*)d_in[7];
    const float* Wres  = (const float*)d_in[8];
    float* out         = (float*)d_out;

    int M = in_sizes[0] / DIM;       // 50000
    int E = in_sizes[1] / 2;         // 600000
    int n4 = M * (DIM / 4);

    static int configured = 0;
    if (!configured) {
        cudaFuncSetAttribute(gemm_kernel<1>,
                             cudaFuncAttributeMaxDynamicSharedMemorySize, SMEM_BYTES);
        cudaFuncSetAttribute(gemm_kernel<2>,
                             cudaFuncAttributeMaxDynamicSharedMemorySize, SMEM_BYTES);
        configured = 1;
    }

    init_kernel<<<(n4 + 255) / 256, 256>>>(x, W1, W2, Wres, n4);
    {
        long long work = (long long)E * 32;
        int blocks = (int)((work + 255) / 256);
        scatter_kernel<<<blocks, 256>>>(x, ei, E);
    }
    int gb = (M + BM - 1) / BM;
    float invM = 1.0f / (float)M;
    gemm_kernel<1><<<gb, NTHREADS, SMEM_BYTES>>>(nullptr, b1, nullptr, nullptr, nullptr, M, invM);
    gemm_kernel<2><<<gb, NTHREADS, SMEM_BYTES>>>(x, b2, gamma, beta, out, M, invM);
}

// round 11
// speedup vs baseline: 1.0154x; 1.0154x over previous
#include <cuda_runtime.h>
#include <cstdint>

#define DIM 128
#define MAXN 50176
#define BM 128
#define BK 32
#define AP 36                   // padded smem row pitch (words), conflict-free
#define TILEW (BM * AP)         // 4608 words per tile buffer
#define NSTAGE 3
#define SMEM_BYTES (2 * NSTAGE * TILEW * 4)   // 3 A bufs + 3 W bufs = 110592 B

__device__ float g_hpre[MAXN * DIM];       // x + agg
__device__ float g_h1[MAXN * DIM];         // Linear1 out (raw, pre-BN)
__device__ float g_stats[2 * DIM];         // colsum | colsumsq
__device__ unsigned g_w1[DIM * DIM];       // tf32-rounded weights
__device__ unsigned g_w2[DIM * DIM];
__device__ unsigned g_wres[DIM * DIM];

// ---------------------------------------------------------------------------
__device__ __forceinline__ unsigned f2tf(float f) {
    unsigned r;
    asm("cvt.rna.tf32.f32 %0, %1;" : "=r"(r) : "f"(f));
    return r;
}

__device__ __forceinline__ void mma_tf32(float* c, const unsigned* a, const unsigned* b) {
    asm volatile(
        "mma.sync.aligned.m16n8k8.row.col.f32.tf32.tf32.f32 "
        "{%0,%1,%2,%3}, {%4,%5,%6,%7}, {%8,%9}, {%0,%1,%2,%3};"
        : "+f"(c[0]), "+f"(c[1]), "+f"(c[2]), "+f"(c[3])
        : "r"(a[0]), "r"(a[1]), "r"(a[2]), "r"(a[3]), "r"(b[0]), "r"(b[1]));
}

__device__ __forceinline__ void cp16(unsigned smem_dst, const void* gsrc) {
    asm volatile("cp.async.ca.shared.global [%0], [%1], 16;"
                 :: "r"(smem_dst), "l"(gsrc));
}

__device__ __forceinline__ void ldsm4(unsigned& r0, unsigned& r1,
                                      unsigned& r2, unsigned& r3,
                                      const unsigned* p) {
    unsigned addr = (unsigned)__cvta_generic_to_shared(p);
    asm volatile("ldmatrix.sync.aligned.m8n8.x4.shared.b16 {%0,%1,%2,%3}, [%4];"
                 : "=r"(r0), "=r"(r1), "=r"(r2), "=r"(r3) : "r"(addr));
}

// ---------------------------------------------------------------------------
// init: copy x -> g_hpre ; round weights ; zero stats   (one launch)
// ---------------------------------------------------------------------------
__global__ void init_kernel(const float* __restrict__ x,
                            const float* __restrict__ W1,
                            const float* __restrict__ W2,
                            const float* __restrict__ Wres, int n4) {
    int gid = blockIdx.x * blockDim.x + threadIdx.x;
    if (gid < 2 * DIM) g_stats[gid] = 0.0f;
    if (gid < DIM * DIM) {
        g_w1[gid]   = f2tf(W1[gid]);
        g_w2[gid]   = f2tf(W2[gid]);
        g_wres[gid] = f2tf(Wres[gid]);
    }
    if (gid < n4) ((float4*)g_hpre)[gid] = ((const float4*)x)[gid];
}

// ---------------------------------------------------------------------------
// scatter-add: warp per edge, lane = 4 floats -> LDG.128 + red.global.v4.f32
// ---------------------------------------------------------------------------
__global__ void scatter_kernel(const float* __restrict__ x,
                               const int* __restrict__ ei,
                               int n_edges) {
    int g = blockIdx.x * blockDim.x + threadIdx.x;
    int e = g >> 5;
    int lane = g & 31;
    if (e >= n_edges) return;
    int src = ei[e];
    int dst = ei[n_edges + e];
    const float4* xs = (const float4*)(x + (size_t)src * DIM) + lane;
    float4* hd = (float4*)(g_hpre + (size_t)dst * DIM) + lane;
    float4 v = __ldg(xs);
    asm volatile("red.global.add.v4.f32 [%0], {%1, %2, %3, %4};"
                 :: "l"(hd), "f"(v.x), "f"(v.y), "f"(v.z), "f"(v.w)
                 : "memory");
}

// ---------------------------------------------------------------------------
// 3-stage pipelined tf32 GEMM: 256 thr, 8 warps 4x2, 32x64 warp tiles,
// ONE barrier per chunk, prefetch depth 2.
// PHASE 1: h1 = h_pre @ W1^T + b1 ; BN column sum/sumsq        (K=128)
// PHASE 2: out = lrelu_.2( bnlrelu(h1) @ W2^T + x @ Wres^T + b2 )  (K=256)
// ---------------------------------------------------------------------------
template <int PHASE>
__global__ __launch_bounds__(256, 2)
void gemm_kernel(const float* __restrict__ Ax,      // phase2: x
                 const float* __restrict__ bias,
                 const float* __restrict__ gamma,
                 const float* __restrict__ beta,
                 float* __restrict__ outp,
                 int M, float invM) {
    extern __shared__ unsigned smem[];
    unsigned* Abuf = smem;                      // [NSTAGE][TILEW]
    unsigned* Wbuf = smem + NSTAGE * TILEW;     // [NSTAGE][TILEW]
    __shared__ float s_sum[DIM];
    __shared__ float s_sq[DIM];
    __shared__ float ssc[DIM];
    __shared__ float ssh[DIM];

    const int tid  = threadIdx.x;
    const int wid  = tid >> 5;
    const int lane = tid & 31;
    const int g    = lane >> 2;
    const int tg   = lane & 3;
    const int lm   = lane >> 3;        // ldmatrix: matrix id 0..3
    const int lr   = lane & 7;         // ldmatrix: row within matrix
    const int wm   = wid & 3;          // m tile of 32
    const int wn   = wid >> 2;         // n tile of 64
    const int rowBase = blockIdx.x * BM;

    if (PHASE == 1) {
        if (tid < DIM) { s_sum[tid] = 0.f; s_sq[tid] = 0.f; }
    } else {
        if (tid < DIM) {
            float mu  = g_stats[tid] * invM;
            float var = g_stats[DIM + tid] * invM - mu * mu;
            float rstd = rsqrtf(var + 1e-5f);
            float s = gamma[tid] * rstd;
            ssc[tid] = s;
            ssh[tid] = beta[tid] - mu * s;
        }
    }

    const int NCHUNK = (PHASE == 1) ? 4 : 8;

    // ---- chunk loader: 4 x 16B cp.async for A, 4 for W, one commit ----
    auto load_chunk = [&](int kc, int bufidx) {
        const int kbase = kc * BK;
        unsigned* Ad = Abuf + bufidx * TILEW;
        unsigned* Wd = Wbuf + bufidx * TILEW;
#pragma unroll
        for (int t = 0; t < 4; t++) {
            int idx = tid + t * 256;
            int m = idx >> 3;
            int f4 = (idx & 7) * 4;
            const void* asrc;
            if (PHASE == 1) {
                asrc = g_hpre + (size_t)(rowBase + m) * DIM + kbase + f4;
            } else if (kbase < DIM) {
                asrc = g_h1 + (size_t)(rowBase + m) * DIM + kbase + f4;
            } else {
                int gr = rowBase + m;
                if (gr >= M) gr = M - 1;           // x has exactly M rows
                asrc = Ax + (size_t)gr * DIM + (kbase - DIM) + f4;
            }
            cp16((unsigned)__cvta_generic_to_shared(Ad + m * AP + f4), asrc);
            const unsigned* wsrc;
            if (PHASE == 1)            wsrc = g_w1   + m * DIM + kbase + f4;
            else if (kbase < DIM)      wsrc = g_w2   + m * DIM + kbase + f4;
            else                       wsrc = g_wres + m * DIM + (kbase - DIM) + f4;
            cp16((unsigned)__cvta_generic_to_shared(Wd + m * AP + f4), wsrc);
        }
        asm volatile("cp.async.commit_group;" ::: "memory");
    };

    float acc[2][8][4];
#pragma unroll
    for (int i = 0; i < 2; i++)
#pragma unroll
        for (int j = 0; j < 8; j++)
#pragma unroll
            for (int r = 0; r < 4; r++) acc[i][j][r] = 0.f;

    load_chunk(0, 0);
    load_chunk(1, 1);

    int buf = 0;        // = kc % 3
    int nbuf = 2;       // = (kc+2) % 3

#pragma unroll 1
    for (int kc = 0; kc < NCHUNK; kc++) {
        // ensure chunk kc's group is complete (pending set is {kc, kc+1})
        if (kc + 1 < NCHUNK) {
            asm volatile("cp.async.wait_group 1;" ::: "memory");
        } else {
            asm volatile("cp.async.wait_group 0;" ::: "memory");
        }
        __syncthreads();   // also separates iter kc-1 readers from load(kc+2)

        if (kc + 2 < NCHUNK) load_chunk(kc + 2, nbuf);

        unsigned* As = Abuf + buf * TILEW;
        const unsigned* Ws = Wbuf + buf * TILEW;

        // ---- phase2, h1 chunks: BN + leaky + tf32-round in smem ----
        if (PHASE == 2 && kc * BK < DIM) {
            const int kbase = kc * BK;
#pragma unroll
            for (int t = 0; t < 4; t++) {
                int idx = tid + t * 256;
                int m = idx >> 3;
                int f4 = (idx & 7) * 4;
                unsigned* p = As + m * AP + f4;
                float4 v = *(float4*)p;
                int kk = kbase + f4;
                v.x = fmaf(v.x, ssc[kk + 0], ssh[kk + 0]);
                v.y = fmaf(v.y, ssc[kk + 1], ssh[kk + 1]);
                v.z = fmaf(v.z, ssc[kk + 2], ssh[kk + 2]);
                v.w = fmaf(v.w, ssc[kk + 3], ssh[kk + 3]);
                v.x = v.x > 0.f ? v.x : 0.01f * v.x;
                v.y = v.y > 0.f ? v.y : 0.01f * v.y;
                v.z = v.z > 0.f ? v.z : 0.01f * v.z;
                v.w = v.w > 0.f ? v.w : 0.01f * v.w;
                p[0] = f2tf(v.x); p[1] = f2tf(v.y);
                p[2] = f2tf(v.z); p[3] = f2tf(v.w);
            }
            __syncthreads();
        }

#pragma unroll
        for (int k8 = 0; k8 < 4; k8++) {
            const int kof = k8 * 8;
            unsigned afrag[2][4];
#pragma unroll
            for (int mt = 0; mt < 2; mt++) {
                int r = wm * 32 + mt * 16 + (lm & 1) * 8 + lr;
                ldsm4(afrag[mt][0], afrag[mt][1], afrag[mt][2], afrag[mt][3],
                      As + r * AP + kof + (lm >> 1) * 4);
            }
            unsigned bfrag[8][2];
#pragma unroll
            for (int ntp = 0; ntp < 4; ntp++) {
                int n = wn * 64 + ntp * 16 + (lm >> 1) * 8 + lr;
                ldsm4(bfrag[2 * ntp][0], bfrag[2 * ntp][1],
                      bfrag[2 * ntp + 1][0], bfrag[2 * ntp + 1][1],
                      Ws + n * AP + kof + (lm & 1) * 4);
            }
#pragma unroll
            for (int mt = 0; mt < 2; mt++)
#pragma unroll
                for (int nt = 0; nt < 8; nt++)
                    mma_tf32(acc[mt][nt], afrag[mt], bfrag[nt]);
        }

        buf = (buf == 2) ? 0 : buf + 1;
        nbuf = (nbuf == 2) ? 0 : nbuf + 1;
    }
    __syncthreads();   // protect epilogue smem reuse ordering

    // ---- epilogue ----
    if (PHASE == 1) {
        float tsum[8][2], tsq[8][2];
#pragma unroll
        for (int nt = 0; nt < 8; nt++)
            tsum[nt][0] = tsum[nt][1] = tsq[nt][0] = tsq[nt][1] = 0.f;

#pragma unroll
        for (int mt = 0; mt < 2; mt++) {
#pragma unroll
            for (int half = 0; half < 2; half++) {
                int gr = rowBase + wm * 32 + mt * 16 + g + half * 8;
                if (gr < M) {
#pragma unroll
                    for (int nt = 0; nt < 8; nt++) {
                        int c = wn * 64 + nt * 8 + tg * 2;
                        float v0 = acc[mt][nt][half * 2 + 0] + __ldg(bias + c);
                        float v1 = acc[mt][nt][half * 2 + 1] + __ldg(bias + c + 1);
                        tsum[nt][0] += v0;  tsum[nt][1] += v1;
                        tsq[nt][0] += v0 * v0;  tsq[nt][1] += v1 * v1;
                        *(float2*)(g_h1 + (size_t)gr * DIM + c) = make_float2(v0, v1);
                    }
                }
            }
        }
#pragma unroll
        for (int nt = 0; nt < 8; nt++) {
#pragma unroll
            for (int h = 0; h < 2; h++) {
#pragma unroll
                for (int ofs = 4; ofs < 32; ofs <<= 1) {
                    tsum[nt][h] += __shfl_xor_sync(0xffffffff, tsum[nt][h], ofs);
                    tsq[nt][h]  += __shfl_xor_sync(0xffffffff, tsq[nt][h], ofs);
                }
            }
        }
        if (g == 0) {
#pragma unroll
            for (int nt = 0; nt < 8; nt++) {
                int c = wn * 64 + nt * 8 + tg * 2;
                atomicAdd(&s_sum[c],     tsum[nt][0]);
                atomicAdd(&s_sum[c + 1], tsum[nt][1]);
                atomicAdd(&s_sq[c],      tsq[nt][0]);
                atomicAdd(&s_sq[c + 1],  tsq[nt][1]);
            }
        }
        __syncthreads();
        if (tid < DIM) {
            atomicAdd(&g_stats[tid],       s_sum[tid]);
            atomicAdd(&g_stats[DIM + tid], s_sq[tid]);
        }
    } else {
#pragma unroll
        for (int mt = 0; mt < 2; mt++) {
#pragma unroll
            for (int half = 0; half < 2; half++) {
                int gr = rowBase + wm * 32 + mt * 16 + g + half * 8;
                if (gr < M) {
#pragma unroll
                    for (int nt = 0; nt < 8; nt++) {
                        int c = wn * 64 + nt * 8 + tg * 2;
                        float v0 = acc[mt][nt][half * 2 + 0] + __ldg(bias + c);
                        float v1 = acc[mt][nt][half * 2 + 1] + __ldg(bias + c + 1);
                        v0 = v0 > 0.f ? v0 : 0.2f * v0;
                        v1 = v1 > 0.f ? v1 : 0.2f * v1;
                        *(float2*)(outp + (size_t)gr * DIM + c) = make_float2(v0, v1);
                    }
                }
            }
        }
    }
}

// ---------------------------------------------------------------------------
extern "C" void kernel_launch(void* const* d_in, const int* in_sizes, int n_in,
                              void* d_out, int out_size) {
    const float* x     = (const float*)d_in[0];
    const int* ei      = (const int*)d_in[1];
    const float* W1    = (const float*)d_in[2];
    const float* b1    = (const float*)d_in[3];
    const float* gamma = (const float*)d_in[4];
    const float* beta  = (const float*)d_in[5];
    const float* W2    = (const float*)d_in[6];
    const float* b2    = (const float*)d_in[7];
    const float* Wres  = (const float*)d_in[8];
    float* out         = (float*)d_out;

    int M = in_sizes[0] / DIM;       // 50000
    int E = in_sizes[1] / 2;         // 600000
    int n4 = M * (DIM / 4);

    static int configured = 0;
    if (!configured) {
        cudaFuncSetAttribute(gemm_kernel<1>,
                             cudaFuncAttributeMaxDynamicSharedMemorySize, SMEM_BYTES);
        cudaFuncSetAttribute(gemm_kernel<2>,
                             cudaFuncAttributeMaxDynamicSharedMemorySize, SMEM_BYTES);
        configured = 1;
    }

    init_kernel<<<(n4 + 255) / 256, 256>>>(x, W1, W2, Wres, n4);
    {
        long long work = (long long)E * 32;
        int blocks = (int)((work + 255) / 256);
        scatter_kernel<<<blocks, 256>>>(x, ei, E);
    }
    int gb = (M + BM - 1) / BM;
    float invM = 1.0f / (float)M;
    gemm_kernel<1><<<gb, 256, SMEM_BYTES>>>(nullptr, b1, nullptr, nullptr, nullptr, M, invM);
    gemm_kernel<2><<<gb, 256, SMEM_BYTES>>>(x, b2, gamma, beta, out, M, invM);
}